// round 2
// baseline (speedup 1.0000x reference)
#include <cuda_runtime.h>
#include <cuda_bf16.h>
#include <math.h>

// ---------------------------------------------------------------------------
// GPT-2 forward (L=12, H=12, C=768, B=2, T=1024, Vp=50304), fp32 baseline.
// Scratch lives in __device__ globals (no allocation allowed).
// ---------------------------------------------------------------------------

#define BT   2048          // B*T
#define CC   768
#define C3   2304          // 3*C
#define C4   3072          // 4*C
#define NH   12
#define HD   64
#define TT   1024
#define VP   50304
#define NL   12

__device__ float g_x  [BT * CC];   // residual stream
__device__ float g_h  [BT * CC];   // layernorm output
__device__ float g_qkv[BT * C3];   // qkv projection
__device__ float g_y  [BT * CC];   // attention output
__device__ float g_fch[BT * C4];   // fc hidden (post-GELU)

// ---------------------------------------------------------------------------
// Embedding: x[b,t,:] = wte[idx[b,t],:] + wpe[t,:]
// ---------------------------------------------------------------------------
__global__ void embed_kernel(const int* __restrict__ idx,
                             const float* __restrict__ wte,
                             const float* __restrict__ wpe,
                             float* __restrict__ x)
{
    int i = blockIdx.x * blockDim.x + threadIdx.x;   // over BT*CC
    int row = i / CC;                                // 0..2047
    int c   = i - row * CC;
    int t   = row & (TT - 1);
    int tok = idx[row];
    x[i] = wte[(size_t)tok * CC + c] + wpe[(size_t)t * CC + c];
}

// ---------------------------------------------------------------------------
// LayerNorm over last dim (768). One block (256 threads) per row.
// ---------------------------------------------------------------------------
__global__ void layernorm_kernel(const float* __restrict__ x,
                                 const float* __restrict__ w,
                                 const float* __restrict__ b,
                                 float* __restrict__ out)
{
    int row = blockIdx.x;
    int tid = threadIdx.x;                // 256 threads, 3 elems each
    const float* xr = x + (size_t)row * CC;

    float v0 = xr[tid];
    float v1 = xr[tid + 256];
    float v2 = xr[tid + 512];

    __shared__ float red[256];
    red[tid] = v0 + v1 + v2;
    __syncthreads();
    #pragma unroll
    for (int o = 128; o > 0; o >>= 1) {
        if (tid < o) red[tid] += red[tid + o];
        __syncthreads();
    }
    float mu = red[0] * (1.0f / CC);
    __syncthreads();

    float d0 = v0 - mu, d1 = v1 - mu, d2 = v2 - mu;
    red[tid] = d0 * d0 + d1 * d1 + d2 * d2;
    __syncthreads();
    #pragma unroll
    for (int o = 128; o > 0; o >>= 1) {
        if (tid < o) red[tid] += red[tid + o];
        __syncthreads();
    }
    float rstd = rsqrtf(red[0] * (1.0f / CC) + 1e-5f);

    float* orow = out + (size_t)row * CC;
    orow[tid]       = d0 * rstd * w[tid]       + b[tid];
    orow[tid + 256] = d1 * rstd * w[tid + 256] + b[tid + 256];
    orow[tid + 512] = d2 * rstd * w[tid + 512] + b[tid + 512];
}

// ---------------------------------------------------------------------------
// GEMM: C[M,N] = A[M,K] @ W[N,K]^T  (+ bias) (+GELU) (+ residual)
// Tiles: 64x64x32, 256 threads, 4x4 per-thread micro-tile.
// All M,N multiples of 64; K multiple of 32 (no bounds checks).
// ---------------------------------------------------------------------------
#define TM 64
#define TN 64
#define TK 32

__global__ void gemm_kernel(const float* __restrict__ A,
                            const float* __restrict__ W,
                            const float* __restrict__ bias,  // may be null
                            const float* __restrict__ res,   // may be null
                            float* __restrict__ C,
                            int M, int N, int K, int act)
{
    __shared__ float As[TK][TM + 4];  // transposed tiles, padded for b-conflicts
    __shared__ float Bs[TK][TN + 4];

    int tx = threadIdx.x;             // 0..15
    int ty = threadIdx.y;             // 0..15
    int tid = ty * 16 + tx;
    int m0 = blockIdx.y * TM;
    int n0 = blockIdx.x * TN;

    float acc[4][4] = {};

    for (int k0 = 0; k0 < K; k0 += TK) {
        // Load 64x32 A tile and 64x32 W tile (one warp per 32-float row chunk).
        #pragma unroll
        for (int i = 0; i < 8; i++) {
            int e = tid + i * 256;
            int r = e >> 5;           // 0..63
            int c = e & 31;           // 0..31
            As[c][r] = A[(size_t)(m0 + r) * K + k0 + c];
            Bs[c][r] = W[(size_t)(n0 + r) * K + k0 + c];
        }
        __syncthreads();

        #pragma unroll
        for (int k = 0; k < TK; k++) {
            float4 a4 = *(const float4*)&As[k][ty * 4];
            float4 b4 = *(const float4*)&Bs[k][tx * 4];
            float a[4] = {a4.x, a4.y, a4.z, a4.w};
            float b[4] = {b4.x, b4.y, b4.z, b4.w};
            #pragma unroll
            for (int i = 0; i < 4; i++)
                #pragma unroll
                for (int j = 0; j < 4; j++)
                    acc[i][j] += a[i] * b[j];
        }
        __syncthreads();
    }

    #pragma unroll
    for (int i = 0; i < 4; i++) {
        int m = m0 + ty * 4 + i;
        #pragma unroll
        for (int j = 0; j < 4; j++) {
            int n = n0 + tx * 4 + j;
            float v = acc[i][j];
            if (bias) v += bias[n];
            if (act == 1) {
                // tanh-approx GELU (matches jax.nn.gelu approximate=True)
                float u = v;
                float u3 = u * u * u;
                v = 0.5f * u * (1.0f + tanhf(0.7978845608028654f * (u + 0.044715f * u3)));
            }
            if (res) v += res[(size_t)m * N + n];
            C[(size_t)m * N + n] = v;
        }
    }
}

// ---------------------------------------------------------------------------
// Causal attention. One block (128 threads) per (b,h,t) query row.
// qkv layout per token row (stride 2304): [q(768) | k(768) | v(768)].
// y layout: (B,T,C) with head h at columns [h*64, h*64+64).
// ---------------------------------------------------------------------------
__global__ void attn_kernel(const float* __restrict__ qkv,
                            float* __restrict__ y)
{
    int t = blockIdx.x;
    int h = blockIdx.y;
    int b = blockIdx.z;
    int tid = threadIdx.x;            // 128

    __shared__ float p[TT];
    __shared__ float qs[HD];
    __shared__ float red[128];

    const float* qp = qkv + ((size_t)(b * TT + t)) * C3 + h * HD;
    if (tid < 16) {
        float4 v = *(const float4*)(qp + tid * 4);
        *(float4*)(qs + tid * 4) = v;
    }
    __syncthreads();

    // --- scores (causal: j <= t) ---
    float lmax = -1e30f;
    for (int j = tid; j <= t; j += 128) {
        const float* kp = qkv + ((size_t)(b * TT + j)) * C3 + CC + h * HD;
        float s = 0.0f;
        #pragma unroll
        for (int d = 0; d < HD; d += 4) {
            float4 kv = *(const float4*)(kp + d);
            s += qs[d] * kv.x + qs[d + 1] * kv.y + qs[d + 2] * kv.z + qs[d + 3] * kv.w;
        }
        s *= 0.125f;                  // 1/sqrt(64)
        p[j] = s;
        lmax = fmaxf(lmax, s);
    }

    red[tid] = lmax;
    __syncthreads();
    #pragma unroll
    for (int o = 64; o > 0; o >>= 1) {
        if (tid < o) red[tid] = fmaxf(red[tid], red[tid + o]);
        __syncthreads();
    }
    float m = red[0];
    __syncthreads();

    // --- exp + sum ---
    float lsum = 0.0f;
    for (int j = tid; j <= t; j += 128) {
        float e = expf(p[j] - m);
        p[j] = e;
        lsum += e;
    }
    red[tid] = lsum;
    __syncthreads();
    #pragma unroll
    for (int o = 64; o > 0; o >>= 1) {
        if (tid < o) red[tid] += red[tid + o];
        __syncthreads();
    }
    float inv = 1.0f / red[0];
    __syncthreads();

    // --- AV: 64 dims x 2 j-halves ---
    int d = tid & 63;
    int half = tid >> 6;
    float acc = 0.0f;
    for (int j = half; j <= t; j += 2) {
        acc += p[j] * qkv[((size_t)(b * TT + j)) * C3 + 2 * CC + h * HD + d];
    }
    red[tid] = acc;
    __syncthreads();
    if (tid < 64) {
        y[((size_t)(b * TT + t)) * CC + h * HD + tid] = (red[tid] + red[tid + 64]) * inv;
    }
}

// ---------------------------------------------------------------------------
// Host launcher
// ---------------------------------------------------------------------------
extern "C" void kernel_launch(void* const* d_in, const int* in_sizes, int n_in,
                              void* d_out, int out_size)
{
    const int*   idx     = (const int*)  d_in[0];
    const float* wte     = (const float*)d_in[1];
    const float* wpe     = (const float*)d_in[2];
    const float* ln1w    = (const float*)d_in[3];
    const float* ln1b    = (const float*)d_in[4];
    const float* qkvw    = (const float*)d_in[5];
    const float* qkvb    = (const float*)d_in[6];
    const float* projw   = (const float*)d_in[7];
    const float* projb   = (const float*)d_in[8];
    const float* ln2w    = (const float*)d_in[9];
    const float* ln2b    = (const float*)d_in[10];
    const float* fcw     = (const float*)d_in[11];
    const float* fcb     = (const float*)d_in[12];
    const float* fcprojw = (const float*)d_in[13];
    const float* fcprojb = (const float*)d_in[14];
    const float* lnfw    = (const float*)d_in[15];
    const float* lnfb    = (const float*)d_in[16];
    float* out = (float*)d_out;

    float *x, *h, *qkv, *y, *fch;
    cudaGetSymbolAddress((void**)&x,   g_x);
    cudaGetSymbolAddress((void**)&h,   g_h);
    cudaGetSymbolAddress((void**)&qkv, g_qkv);
    cudaGetSymbolAddress((void**)&y,   g_y);
    cudaGetSymbolAddress((void**)&fch, g_fch);

    dim3 gblk(16, 16);

    embed_kernel<<<(BT * CC) / 256, 256>>>(idx, wte, wpe, x);

    for (int l = 0; l < NL; l++) {
        const float* l1w = ln1w + (size_t)l * CC;
        const float* l1b = ln1b + (size_t)l * CC;
        const float* qw  = qkvw + (size_t)l * C3 * CC;
        const float* qb  = qkvb + (size_t)l * C3;
        const float* pw  = projw + (size_t)l * CC * CC;
        const float* pb  = projb + (size_t)l * CC;
        const float* l2w = ln2w + (size_t)l * CC;
        const float* l2b = ln2b + (size_t)l * CC;
        const float* fw  = fcw  + (size_t)l * C4 * CC;
        const float* fb  = fcb  + (size_t)l * C4;
        const float* fpw = fcprojw + (size_t)l * CC * C4;
        const float* fpb = fcprojb + (size_t)l * CC;

        // attn block
        layernorm_kernel<<<BT, 256>>>(x, l1w, l1b, h);
        gemm_kernel<<<dim3(C3 / TN, BT / TM), gblk>>>(h, qw, qb, nullptr, qkv,
                                                      BT, C3, CC, 0);
        attn_kernel<<<dim3(TT, NH, 2), 128>>>(qkv, y);
        gemm_kernel<<<dim3(CC / TN, BT / TM), gblk>>>(y, pw, pb, x, x,
                                                      BT, CC, CC, 0);
        // mlp block
        layernorm_kernel<<<BT, 256>>>(x, l2w, l2b, h);
        gemm_kernel<<<dim3(C4 / TN, BT / TM), gblk>>>(h, fw, fb, nullptr, fch,
                                                      BT, C4, CC, 1);
        gemm_kernel<<<dim3(CC / TN, BT / TM), gblk>>>(fch, fpw, fpb, x, x,
                                                      BT, CC, C4, 0);
    }

    // final LN + tied lm_head
    layernorm_kernel<<<BT, 256>>>(x, lnfw, lnfb, h);
    gemm_kernel<<<dim3(VP / TN, BT / TM), gblk>>>(h, wte, nullptr, nullptr, out,
                                                  BT, VP, CC, 0);
}

// round 9
// speedup vs baseline: 1.7222x; 1.7222x over previous
#include <cuda_runtime.h>
#include <cuda_bf16.h>
#include <math.h>
#include <stdint.h>

// ---------------------------------------------------------------------------
// GPT-2 forward (L=12, H=12, C=768, B=2, T=1024, Vp=50304).
// GEMMs on mma.sync tf32 tensor cores (sm_80+ baseline ISA — the harness
// compiles PTX for plain sm_103, so tcgen05/'a'-features are unavailable).
// ---------------------------------------------------------------------------

#define BT   2048          // B*T
#define CC   768
#define C3   2304          // 3*C
#define C4   3072          // 4*C
#define NH   12
#define HD   64
#define TT   1024
#define VP   50304
#define NL   12

__device__ __align__(16) float g_x  [BT * CC];   // residual stream
__device__ __align__(16) float g_h  [BT * CC];   // layernorm output
__device__ __align__(16) float g_qkv[BT * C3];   // qkv projection
__device__ __align__(16) float g_y  [BT * CC];   // attention output
__device__ __align__(16) float g_fch[BT * C4];   // fc hidden (post-GELU)

// ===========================================================================
// helpers
// ===========================================================================
__device__ __forceinline__ uint32_t smem_u32(const void* p) {
    uint32_t a;
    asm("{ .reg .u64 t; cvta.to.shared.u64 t, %1; cvt.u32.u64 %0, t; }"
        : "=r"(a) : "l"(p));
    return a;
}

__device__ __forceinline__ void cp_async16(uint32_t dst, const void* src) {
    asm volatile("cp.async.cg.shared.global [%0], [%1], 16;"
                 :: "r"(dst), "l"(src));
}
#define CP_COMMIT() asm volatile("cp.async.commit_group;" ::: "memory")
#define CP_WAIT(n)  asm volatile("cp.async.wait_group %0;" :: "n"(n) : "memory")

__device__ __forceinline__ uint32_t f2tf32(float f) {
    uint32_t r;
    asm("cvt.rna.tf32.f32 %0, %1;" : "=r"(r) : "f"(f));
    return r;
}

__device__ __forceinline__ void mma_tf32(float* c,
                                         uint32_t a0, uint32_t a1,
                                         uint32_t a2, uint32_t a3,
                                         uint32_t b0, uint32_t b1) {
    asm volatile(
        "mma.sync.aligned.m16n8k8.row.col.f32.tf32.tf32.f32 "
        "{%0,%1,%2,%3}, {%4,%5,%6,%7}, {%8,%9}, {%0,%1,%2,%3};"
        : "+f"(c[0]), "+f"(c[1]), "+f"(c[2]), "+f"(c[3])
        : "r"(a0), "r"(a1), "r"(a2), "r"(a3), "r"(b0), "r"(b1));
}

// ===========================================================================
// tensor-core GEMM: C[M=2048, N] = A[M,K] @ W[N,K]^T (+bias)(+GELU)(+res)
// Block tile 128x128, BK=32, 256 threads (8 warps: 2m x 4n, warp tile 64x32).
// Smem: padded row stride 36 floats -> conflict-free fragment LDS.
// ===========================================================================
#define BKD       32
#define LDSW      36                       // BK + 4 pad
#define TILE_F    (128 * LDSW)             // floats per A (or B) tile
#define STAGE_F   (2 * TILE_F)             // A tile + B tile
#define GEMM_SMEM_BYTES (2 * STAGE_F * 4)  // 2 stages

__device__ __forceinline__ void load_chunk(const float* __restrict__ A,
                                           const float* __restrict__ W,
                                           int K, int m0, int n0, int k0,
                                           uint32_t sA, uint32_t sB, int tid)
{
    #pragma unroll
    for (int i = 0; i < 4; i++) {
        int idx = tid + i * 256;            // 0..1023
        int r   = idx >> 3;                 // 0..127
        int seg = idx & 7;                  // 16B segment within 32-float row
        uint32_t off = (uint32_t)(r * LDSW + seg * 4) * 4;
        cp_async16(sA + off, A + (size_t)(m0 + r) * K + k0 + seg * 4);
        cp_async16(sB + off, W + (size_t)(n0 + r) * K + k0 + seg * 4);
    }
    CP_COMMIT();
}

__global__ void __launch_bounds__(256)
tc_gemm_kernel(const float* __restrict__ A,
               const float* __restrict__ W,
               const float* __restrict__ bias,  // may be null
               const float* __restrict__ res,   // may be null
               float* __restrict__ C,
               int N, int K, int act)
{
    extern __shared__ __align__(16) float smem[];
    uint32_t sbase = smem_u32(smem);
    int tid = threadIdx.x;
    int wid = tid >> 5;
    int lane = tid & 31;
    int lr = lane >> 2;                     // group id 0..7
    int lc = lane & 3;                      // thread-in-group 0..3
    int wm = wid >> 2;                      // 0..1  (64-row slab)
    int wn = wid & 3;                       // 0..3  (32-col slab)
    int m0 = blockIdx.y * 128;
    int n0 = blockIdx.x * 128;
    int NC = K / BKD;

    float acc[4][4][4];
    #pragma unroll
    for (int i = 0; i < 4; i++)
        #pragma unroll
        for (int j = 0; j < 4; j++)
            #pragma unroll
            for (int q = 0; q < 4; q++) acc[i][j][q] = 0.0f;

    // prologue: prefetch chunks 0, 1
    load_chunk(A, W, K, m0, n0, 0,
               sbase, sbase + TILE_F * 4, tid);
    load_chunk(A, W, K, m0, n0, BKD,
               sbase + STAGE_F * 4, sbase + (STAGE_F + TILE_F) * 4, tid);

    for (int c = 0; c < NC; c++) {
        if (c + 1 < NC) { CP_WAIT(1); } else { CP_WAIT(0); }
        __syncthreads();

        const float* As = smem + (c & 1) * STAGE_F;
        const float* Bs = As + TILE_F;

        #pragma unroll
        for (int kk = 0; kk < BKD; kk += 8) {
            uint32_t a[4][4], b[4][2];
            #pragma unroll
            for (int mi = 0; mi < 4; mi++) {
                int r0 = wm * 64 + mi * 16 + lr;
                a[mi][0] = f2tf32(As[(r0)     * LDSW + kk + lc]);
                a[mi][1] = f2tf32(As[(r0 + 8) * LDSW + kk + lc]);
                a[mi][2] = f2tf32(As[(r0)     * LDSW + kk + lc + 4]);
                a[mi][3] = f2tf32(As[(r0 + 8) * LDSW + kk + lc + 4]);
            }
            #pragma unroll
            for (int ni = 0; ni < 4; ni++) {
                int nr = wn * 32 + ni * 8 + lr;
                b[ni][0] = f2tf32(Bs[nr * LDSW + kk + lc]);
                b[ni][1] = f2tf32(Bs[nr * LDSW + kk + lc + 4]);
            }
            #pragma unroll
            for (int mi = 0; mi < 4; mi++)
                #pragma unroll
                for (int ni = 0; ni < 4; ni++)
                    mma_tf32(acc[mi][ni],
                             a[mi][0], a[mi][1], a[mi][2], a[mi][3],
                             b[ni][0], b[ni][1]);
        }
        __syncthreads();

        if (c + 2 < NC) {
            uint32_t sA = sbase + (c & 1) * STAGE_F * 4;
            load_chunk(A, W, K, m0, n0, (c + 2) * BKD,
                       sA, sA + TILE_F * 4, tid);
        }
    }

    // ---- epilogue: direct float2 stores (32B-sector friendly) ----
    #pragma unroll
    for (int mi = 0; mi < 4; mi++) {
        int row0 = m0 + wm * 64 + mi * 16 + lr;
        #pragma unroll
        for (int ni = 0; ni < 4; ni++) {
            int col = n0 + wn * 32 + ni * 8 + lc * 2;
            float bv0 = 0.0f, bv1 = 0.0f;
            if (bias) { bv0 = __ldg(bias + col); bv1 = __ldg(bias + col + 1); }
            #pragma unroll
            for (int hrow = 0; hrow < 2; hrow++) {
                int row = row0 + hrow * 8;
                float v0 = acc[mi][ni][hrow * 2 + 0] + bv0;
                float v1 = acc[mi][ni][hrow * 2 + 1] + bv1;
                if (act) {
                    float u = v0, u3 = u * u * u;
                    v0 = 0.5f * u * (1.0f + tanhf(0.7978845608028654f * (u + 0.044715f * u3)));
                    u = v1; u3 = u * u * u;
                    v1 = 0.5f * u * (1.0f + tanhf(0.7978845608028654f * (u + 0.044715f * u3)));
                }
                size_t o = (size_t)row * N + col;
                if (res) {
                    float2 rr = *(const float2*)(res + o);
                    v0 += rr.x; v1 += rr.y;
                }
                *(float2*)(C + o) = make_float2(v0, v1);
            }
        }
    }
}

// ---------------------------------------------------------------------------
// Embedding: x[b,t,:] = wte[idx[b,t],:] + wpe[t,:]
// ---------------------------------------------------------------------------
__global__ void embed_kernel(const int* __restrict__ idx,
                             const float* __restrict__ wte,
                             const float* __restrict__ wpe,
                             float* __restrict__ x)
{
    int i = blockIdx.x * blockDim.x + threadIdx.x;
    int row = i / CC;
    int c   = i - row * CC;
    int t   = row & (TT - 1);
    int tok = idx[row];
    x[i] = wte[(size_t)tok * CC + c] + wpe[(size_t)t * CC + c];
}

// ---------------------------------------------------------------------------
// LayerNorm over last dim (768). One block (256 threads) per row.
// ---------------------------------------------------------------------------
__global__ void layernorm_kernel(const float* __restrict__ x,
                                 const float* __restrict__ w,
                                 const float* __restrict__ b,
                                 float* __restrict__ out)
{
    int row = blockIdx.x;
    int tid = threadIdx.x;
    const float* xr = x + (size_t)row * CC;

    float v0 = xr[tid];
    float v1 = xr[tid + 256];
    float v2 = xr[tid + 512];

    __shared__ float red[256];
    red[tid] = v0 + v1 + v2;
    __syncthreads();
    #pragma unroll
    for (int o = 128; o > 0; o >>= 1) {
        if (tid < o) red[tid] += red[tid + o];
        __syncthreads();
    }
    float mu = red[0] * (1.0f / CC);
    __syncthreads();

    float d0 = v0 - mu, d1 = v1 - mu, d2 = v2 - mu;
    red[tid] = d0 * d0 + d1 * d1 + d2 * d2;
    __syncthreads();
    #pragma unroll
    for (int o = 128; o > 0; o >>= 1) {
        if (tid < o) red[tid] += red[tid + o];
        __syncthreads();
    }
    float rstd = rsqrtf(red[0] * (1.0f / CC) + 1e-5f);

    float* orow = out + (size_t)row * CC;
    orow[tid]       = d0 * rstd * w[tid]       + b[tid];
    orow[tid + 256] = d1 * rstd * w[tid + 256] + b[tid + 256];
    orow[tid + 512] = d2 * rstd * w[tid + 512] + b[tid + 512];
}

// ---------------------------------------------------------------------------
// Causal attention. One block (128 threads) per (b,h,t) query row.
// ---------------------------------------------------------------------------
__global__ void attn_kernel(const float* __restrict__ qkv,
                            float* __restrict__ y)
{
    int t = blockIdx.x;
    int h = blockIdx.y;
    int b = blockIdx.z;
    int tid = threadIdx.x;

    __shared__ float p[TT];
    __shared__ float qs[HD];
    __shared__ float red[128];

    const float* qp = qkv + ((size_t)(b * TT + t)) * C3 + h * HD;
    if (tid < 16) {
        float4 v = *(const float4*)(qp + tid * 4);
        *(float4*)(qs + tid * 4) = v;
    }
    __syncthreads();

    float lmax = -1e30f;
    for (int j = tid; j <= t; j += 128) {
        const float* kp = qkv + ((size_t)(b * TT + j)) * C3 + CC + h * HD;
        float s = 0.0f;
        #pragma unroll
        for (int d = 0; d < HD; d += 4) {
            float4 kv = *(const float4*)(kp + d);
            s += qs[d] * kv.x + qs[d + 1] * kv.y + qs[d + 2] * kv.z + qs[d + 3] * kv.w;
        }
        s *= 0.125f;
        p[j] = s;
        lmax = fmaxf(lmax, s);
    }

    red[tid] = lmax;
    __syncthreads();
    #pragma unroll
    for (int o = 64; o > 0; o >>= 1) {
        if (tid < o) red[tid] = fmaxf(red[tid], red[tid + o]);
        __syncthreads();
    }
    float m = red[0];
    __syncthreads();

    float lsum = 0.0f;
    for (int j = tid; j <= t; j += 128) {
        float e = expf(p[j] - m);
        p[j] = e;
        lsum += e;
    }
    red[tid] = lsum;
    __syncthreads();
    #pragma unroll
    for (int o = 64; o > 0; o >>= 1) {
        if (tid < o) red[tid] += red[tid + o];
        __syncthreads();
    }
    float inv = 1.0f / red[0];
    __syncthreads();

    int d = tid & 63;
    int half = tid >> 6;
    float acc = 0.0f;
    for (int j = half; j <= t; j += 2) {
        acc += p[j] * qkv[((size_t)(b * TT + j)) * C3 + 2 * CC + h * HD + d];
    }
    red[tid] = acc;
    __syncthreads();
    if (tid < 64) {
        y[((size_t)(b * TT + t)) * CC + h * HD + tid] = (red[tid] + red[tid + 64]) * inv;
    }
}

// ---------------------------------------------------------------------------
// Host launcher
// ---------------------------------------------------------------------------
static void launch_gemm(const float* A, const float* W, const float* bias,
                        const float* res, float* C, int N, int K, int act)
{
    dim3 grid(N / 128, BT / 128);
    tc_gemm_kernel<<<grid, 256, GEMM_SMEM_BYTES>>>(A, W, bias, res, C, N, K, act);
}

extern "C" void kernel_launch(void* const* d_in, const int* in_sizes, int n_in,
                              void* d_out, int out_size)
{
    const int*   idx     = (const int*)  d_in[0];
    const float* wte     = (const float*)d_in[1];
    const float* wpe     = (const float*)d_in[2];
    const float* ln1w    = (const float*)d_in[3];
    const float* ln1b    = (const float*)d_in[4];
    const float* qkvw    = (const float*)d_in[5];
    const float* qkvb    = (const float*)d_in[6];
    const float* projw   = (const float*)d_in[7];
    const float* projb   = (const float*)d_in[8];
    const float* ln2w    = (const float*)d_in[9];
    const float* ln2b    = (const float*)d_in[10];
    const float* fcw     = (const float*)d_in[11];
    const float* fcb     = (const float*)d_in[12];
    const float* fcprojw = (const float*)d_in[13];
    const float* fcprojb = (const float*)d_in[14];
    const float* lnfw    = (const float*)d_in[15];
    const float* lnfb    = (const float*)d_in[16];
    float* out = (float*)d_out;

    cudaFuncSetAttribute(tc_gemm_kernel,
                         cudaFuncAttributeMaxDynamicSharedMemorySize,
                         GEMM_SMEM_BYTES);

    float *x, *h, *qkv, *y, *fch;
    cudaGetSymbolAddress((void**)&x,   g_x);
    cudaGetSymbolAddress((void**)&h,   g_h);
    cudaGetSymbolAddress((void**)&qkv, g_qkv);
    cudaGetSymbolAddress((void**)&y,   g_y);
    cudaGetSymbolAddress((void**)&fch, g_fch);

    embed_kernel<<<(BT * CC) / 256, 256>>>(idx, wte, wpe, x);

    for (int l = 0; l < NL; l++) {
        const float* l1w = ln1w + (size_t)l * CC;
        const float* l1b = ln1b + (size_t)l * CC;
        const float* qw  = qkvw + (size_t)l * C3 * CC;
        const float* qb  = qkvb + (size_t)l * C3;
        const float* pw  = projw + (size_t)l * CC * CC;
        const float* pb  = projb + (size_t)l * CC;
        const float* l2w = ln2w + (size_t)l * CC;
        const float* l2b = ln2b + (size_t)l * CC;
        const float* fw  = fcw  + (size_t)l * C4 * CC;
        const float* fb  = fcb  + (size_t)l * C4;
        const float* fpw = fcprojw + (size_t)l * CC * C4;
        const float* fpb = fcprojb + (size_t)l * CC;

        layernorm_kernel<<<BT, 256>>>(x, l1w, l1b, h);
        launch_gemm(h, qw, qb, nullptr, qkv, C3, CC, 0);
        attn_kernel<<<dim3(TT, NH, 2), 128>>>(qkv, y);
        launch_gemm(y, pw, pb, x, x, CC, CC, 0);

        layernorm_kernel<<<BT, 256>>>(x, l2w, l2b, h);
        launch_gemm(h, fw, fb, nullptr, fch, C4, CC, 1);
        launch_gemm(fch, fpw, fpb, x, x, CC, C4, 0);
    }

    layernorm_kernel<<<BT, 256>>>(x, lnfw, lnfb, h);
    launch_gemm(h, wte, nullptr, nullptr, out, VP, CC, 0);
}

// round 10
// speedup vs baseline: 3.3455x; 1.9425x over previous
#include <cuda_runtime.h>
#include <cuda_bf16.h>
#include <math.h>
#include <stdint.h>

// ---------------------------------------------------------------------------
// GPT-2 forward (L=12, H=12, C=768, B=2, T=1024, Vp=50304).
// GEMMs: mma.sync tf32 tensor cores, cp.async double-buffer + smem convert
// pass (tf32 conversion once per element, pair-permuted for LDS.64 frags).
// Attention: flash-style 64-query tiles with online softmax.
// ---------------------------------------------------------------------------

#define BT   2048          // B*T
#define CC   768
#define C3   2304          // 3*C
#define C4   3072          // 4*C
#define NH   12
#define HD   64
#define TT   1024
#define VP   50304
#define NL   12

__device__ __align__(16) float g_x  [BT * CC];   // residual stream
__device__ __align__(16) float g_h  [BT * CC];   // layernorm output
__device__ __align__(16) float g_qkv[BT * C3];   // qkv projection
__device__ __align__(16) float g_y  [BT * CC];   // attention output
__device__ __align__(16) float g_fch[BT * C4];   // fc hidden (post-GELU)

// ===========================================================================
// helpers
// ===========================================================================
__device__ __forceinline__ uint32_t smem_u32(const void* p) {
    uint32_t a;
    asm("{ .reg .u64 t; cvta.to.shared.u64 t, %1; cvt.u32.u64 %0, t; }"
        : "=r"(a) : "l"(p));
    return a;
}

__device__ __forceinline__ void cp_async16(uint32_t dst, const void* src) {
    asm volatile("cp.async.cg.shared.global [%0], [%1], 16;"
                 :: "r"(dst), "l"(src));
}
#define CP_COMMIT() asm volatile("cp.async.commit_group;" ::: "memory")
#define CP_WAIT(n)  asm volatile("cp.async.wait_group %0;" :: "n"(n) : "memory")

__device__ __forceinline__ uint32_t f2tf32(float f) {
    uint32_t r;
    asm("cvt.rna.tf32.f32 %0, %1;" : "=r"(r) : "f"(f));
    return r;
}

__device__ __forceinline__ void mma_tf32(float* c,
                                         uint32_t a0, uint32_t a1,
                                         uint32_t a2, uint32_t a3,
                                         uint32_t b0, uint32_t b1) {
    asm volatile(
        "mma.sync.aligned.m16n8k8.row.col.f32.tf32.tf32.f32 "
        "{%0,%1,%2,%3}, {%4,%5,%6,%7}, {%8,%9}, {%0,%1,%2,%3};"
        : "+f"(c[0]), "+f"(c[1]), "+f"(c[2]), "+f"(c[3])
        : "r"(a0), "r"(a1), "r"(a2), "r"(a3), "r"(b0), "r"(b1));
}

// ===========================================================================
// tensor-core GEMM: C[M=2048, N] = A[M,K] @ W[N,K]^T (+bias)(+GELU)(+res)
// Block tile 128x128, BK=32, 256 threads (8 warps: 2m x 4n, warp tile 64x32).
// raw stages (cp.async dest, fp32) -> convert pass -> conv buffer
// (tf32 bits, pair-permuted so fragment pairs are LDS.64).
// ===========================================================================
#define BKD       32
#define LDSW      36                        // row stride in floats (144B, 16B-aligned)
#define TILE_F    (128 * LDSW)              // 4608 floats per tile
#define RAW_OFF(s, w)  (((s) * 2 + (w)) * TILE_F)
#define CONV_OFF(w)    ((4 + (w)) * TILE_F)
#define GEMM_SMEM_BYTES (6 * TILE_F * 4)    // 110592 B

__device__ __forceinline__ void load_chunk(const float* __restrict__ A,
                                           const float* __restrict__ W,
                                           int K, int m0, int n0, int k0,
                                           uint32_t sA, uint32_t sB, int tid)
{
    #pragma unroll
    for (int i = 0; i < 4; i++) {
        int idx = tid + i * 256;            // 0..1023
        int r   = idx >> 3;                 // 0..127
        int seg = idx & 7;                  // 16B segment within 32-float row
        uint32_t off = (uint32_t)(r * LDSW + seg * 4) * 4;
        cp_async16(sA + off, A + (size_t)(m0 + r) * K + k0 + seg * 4);
        cp_async16(sB + off, W + (size_t)(n0 + r) * K + k0 + seg * 4);
    }
    CP_COMMIT();
}

__global__ void __launch_bounds__(256)
tc_gemm_kernel(const float* __restrict__ A,
               const float* __restrict__ W,
               const float* __restrict__ bias,  // may be null
               const float* __restrict__ res,   // may be null
               float* __restrict__ C,
               int N, int K, int act)
{
    extern __shared__ __align__(16) float smem[];
    uint32_t sbase = smem_u32(smem);
    int tid = threadIdx.x;
    int wid = tid >> 5;
    int lane = tid & 31;
    int lr = lane >> 2;                     // group id 0..7
    int lc = lane & 3;                      // thread-in-group 0..3
    int wm = wid >> 2;                      // 0..1  (64-row slab)
    int wn = wid & 3;                       // 0..3  (32-col slab)
    int m0 = blockIdx.y * 128;
    int n0 = blockIdx.x * 128;
    int NC = K / BKD;

    float acc[4][4][4];
    #pragma unroll
    for (int i = 0; i < 4; i++)
        #pragma unroll
        for (int j = 0; j < 4; j++)
            #pragma unroll
            for (int q = 0; q < 4; q++) acc[i][j][q] = 0.0f;

    // prologue: prefetch chunks 0, 1
    load_chunk(A, W, K, m0, n0, 0,
               sbase + RAW_OFF(0, 0) * 4, sbase + RAW_OFF(0, 1) * 4, tid);
    load_chunk(A, W, K, m0, n0, BKD,
               sbase + RAW_OFF(1, 0) * 4, sbase + RAW_OFF(1, 1) * 4, tid);

    const float* convA = smem + CONV_OFF(0);
    const float* convB = smem + CONV_OFF(1);

    for (int c = 0; c < NC; c++) {
        if (c + 1 < NC) { CP_WAIT(1); } else { CP_WAIT(0); }
        __syncthreads();

        // ---- convert pass: fp32 raw -> tf32 bits, pair-permuted ----
        // group layout: [q0,q4,q1,q5,q2,q6,q3,q7] per 8-float k-group
        {
            const float* rawBase = smem + RAW_OFF(c & 1, 0);
            #pragma unroll
            for (int i = 0; i < 4; i++) {
                int seg  = tid + i * 256;           // 0..1023
                int tile = seg >> 9;                // 0 = A, 1 = B
                int r    = (seg >> 2) & 127;
                int g    = seg & 3;
                const float* rp = rawBase + tile * TILE_F + r * LDSW + g * 8;
                float4 x0 = *(const float4*)rp;
                float4 x1 = *(const float4*)(rp + 4);
                uint32_t c0 = f2tf32(x0.x), c1 = f2tf32(x0.y);
                uint32_t c2 = f2tf32(x0.z), c3 = f2tf32(x0.w);
                uint32_t c4 = f2tf32(x1.x), c5 = f2tf32(x1.y);
                uint32_t c6 = f2tf32(x1.z), c7 = f2tf32(x1.w);
                uint32_t* wp = (uint32_t*)(smem + CONV_OFF(tile) + r * LDSW + g * 8);
                *(uint4*)wp       = make_uint4(c0, c4, c1, c5);
                *(uint4*)(wp + 4) = make_uint4(c2, c6, c3, c7);
            }
        }
        __syncthreads();

        // raw[c&1] consumed -> prefetch chunk c+2 into it
        if (c + 2 < NC) {
            load_chunk(A, W, K, m0, n0, (c + 2) * BKD,
                       sbase + RAW_OFF(c & 1, 0) * 4,
                       sbase + RAW_OFF(c & 1, 1) * 4, tid);
        }

        // ---- mma mainloop on converted data (no CVT, LDS.64 fragments) ----
        #pragma unroll
        for (int g = 0; g < 4; g++) {
            int base = g * 8 + 2 * lc;
            float2 aLo[4], aHi[4];
            float2 bb[4];
            #pragma unroll
            for (int mi = 0; mi < 4; mi++) {
                int r0 = wm * 64 + mi * 16 + lr;
                aLo[mi] = *(const float2*)&convA[r0 * LDSW + base];        // a0, a2
                aHi[mi] = *(const float2*)&convA[(r0 + 8) * LDSW + base];  // a1, a3
            }
            #pragma unroll
            for (int ni = 0; ni < 4; ni++) {
                int nr = wn * 32 + ni * 8 + lr;
                bb[ni] = *(const float2*)&convB[nr * LDSW + base];         // b0, b1
            }
            #pragma unroll
            for (int mi = 0; mi < 4; mi++)
                #pragma unroll
                for (int ni = 0; ni < 4; ni++)
                    mma_tf32(acc[mi][ni],
                             __float_as_uint(aLo[mi].x), __float_as_uint(aHi[mi].x),
                             __float_as_uint(aLo[mi].y), __float_as_uint(aHi[mi].y),
                             __float_as_uint(bb[ni].x),  __float_as_uint(bb[ni].y));
        }
        __syncthreads();   // conv buffer free for next chunk's convert
    }

    // ---- epilogue: direct float2 stores ----
    #pragma unroll
    for (int mi = 0; mi < 4; mi++) {
        int row0 = m0 + wm * 64 + mi * 16 + lr;
        #pragma unroll
        for (int ni = 0; ni < 4; ni++) {
            int col = n0 + wn * 32 + ni * 8 + lc * 2;
            float bv0 = 0.0f, bv1 = 0.0f;
            if (bias) { bv0 = __ldg(bias + col); bv1 = __ldg(bias + col + 1); }
            #pragma unroll
            for (int hrow = 0; hrow < 2; hrow++) {
                int row = row0 + hrow * 8;
                float v0 = acc[mi][ni][hrow * 2 + 0] + bv0;
                float v1 = acc[mi][ni][hrow * 2 + 1] + bv1;
                if (act) {
                    float u = v0, u3 = u * u * u;
                    v0 = 0.5f * u * (1.0f + tanhf(0.7978845608028654f * (u + 0.044715f * u3)));
                    u = v1; u3 = u * u * u;
                    v1 = 0.5f * u * (1.0f + tanhf(0.7978845608028654f * (u + 0.044715f * u3)));
                }
                size_t o = (size_t)row * N + col;
                if (res) {
                    float2 rr = *(const float2*)(res + o);
                    v0 += rr.x; v1 += rr.y;
                }
                *(float2*)(C + o) = make_float2(v0, v1);
            }
        }
    }
}

// ---------------------------------------------------------------------------
// Embedding: x[b,t,:] = wte[idx[b,t],:] + wpe[t,:]
// ---------------------------------------------------------------------------
__global__ void embed_kernel(const int* __restrict__ idx,
                             const float* __restrict__ wte,
                             const float* __restrict__ wpe,
                             float* __restrict__ x)
{
    int i = blockIdx.x * blockDim.x + threadIdx.x;
    int row = i / CC;
    int c   = i - row * CC;
    int t   = row & (TT - 1);
    int tok = idx[row];
    x[i] = wte[(size_t)tok * CC + c] + wpe[(size_t)t * CC + c];
}

// ---------------------------------------------------------------------------
// LayerNorm over last dim (768). One block (256 threads) per row.
// ---------------------------------------------------------------------------
__global__ void layernorm_kernel(const float* __restrict__ x,
                                 const float* __restrict__ w,
                                 const float* __restrict__ b,
                                 float* __restrict__ out)
{
    int row = blockIdx.x;
    int tid = threadIdx.x;
    const float* xr = x + (size_t)row * CC;

    float v0 = xr[tid];
    float v1 = xr[tid + 256];
    float v2 = xr[tid + 512];

    __shared__ float red[256];
    red[tid] = v0 + v1 + v2;
    __syncthreads();
    #pragma unroll
    for (int o = 128; o > 0; o >>= 1) {
        if (tid < o) red[tid] += red[tid + o];
        __syncthreads();
    }
    float mu = red[0] * (1.0f / CC);
    __syncthreads();

    float d0 = v0 - mu, d1 = v1 - mu, d2 = v2 - mu;
    red[tid] = d0 * d0 + d1 * d1 + d2 * d2;
    __syncthreads();
    #pragma unroll
    for (int o = 128; o > 0; o >>= 1) {
        if (tid < o) red[tid] += red[tid + o];
        __syncthreads();
    }
    float rstd = rsqrtf(red[0] * (1.0f / CC) + 1e-5f);

    float* orow = out + (size_t)row * CC;
    orow[tid]       = d0 * rstd * w[tid]       + b[tid];
    orow[tid + 256] = d1 * rstd * w[tid + 256] + b[tid + 256];
    orow[tid + 512] = d2 * rstd * w[tid + 512] + b[tid + 512];
}

// ---------------------------------------------------------------------------
// Flash-style causal attention.
// Block = 64 queries x 1 head; 256 threads = 8 warps x 8 queries each.
// K/V tiles (64x64) staged in smem, online softmax, per-warp P buffer.
// ---------------------------------------------------------------------------
#define AT_KS   0                          // K tile: 64 x 68
#define AT_VS   (64 * 68)                  // V tile: 64 x 68
#define AT_QS   (2 * 64 * 68)              // Q: 64 rows x 68
#define AT_PS   (3 * 64 * 68)              // P: 64 rows x 64
#define ATTN_SMEM_BYTES ((3 * 64 * 68 + 64 * 64) * 4)

__global__ void __launch_bounds__(256)
attn_kernel2(const float* __restrict__ qkv, float* __restrict__ y)
{
    extern __shared__ __align__(16) float asm_[];
    float* S_K = asm_ + AT_KS;
    float* S_V = asm_ + AT_VS;
    float* S_Q = asm_ + AT_QS;
    float* S_P = asm_ + AT_PS;

    int qt = blockIdx.x;                   // query tile (16)
    int h  = blockIdx.y;
    int b  = blockIdx.z;
    int tid = threadIdx.x;
    int warp = tid >> 5;
    int lane = tid & 31;

    // ---- load Q rows for this warp (8 rows x 64 floats) ----
    #pragma unroll
    for (int i = 0; i < 4; i++) {
        int u  = lane + i * 32;            // 0..127
        int qi = u >> 4;
        int d4 = u & 15;
        int q  = qt * 64 + warp * 8 + qi;
        float4 v = *(const float4*)&qkv[((size_t)(b * TT + q)) * C3 + h * HD + d4 * 4];
        *(float4*)&S_Q[(warp * 8 + qi) * 68 + d4 * 4] = v;
    }

    float m[8], l[8], a0[8], a1[8];
    #pragma unroll
    for (int qi = 0; qi < 8; qi++) { m[qi] = -1e30f; l[qi] = 0.0f; a0[qi] = 0.0f; a1[qi] = 0.0f; }

    for (int jt = 0; jt <= qt; jt++) {
        __syncthreads();
        // ---- load K/V tile (64 rows x 64 floats each) ----
        #pragma unroll
        for (int i = 0; i < 4; i++) {
            int u  = tid + i * 256;        // 0..1023
            int j  = u >> 4;
            int d4 = u & 15;
            size_t gb = ((size_t)(b * TT + jt * 64 + j)) * C3 + h * HD + d4 * 4;
            *(float4*)&S_K[j * 68 + d4 * 4] = *(const float4*)&qkv[gb + CC];
            *(float4*)&S_V[j * 68 + d4 * 4] = *(const float4*)&qkv[gb + 2 * CC];
        }
        __syncthreads();

        // ---- scores: this lane owns j = lane and j = lane+32 ----
        float s0[8], s1[8];
        #pragma unroll
        for (int qi = 0; qi < 8; qi++) { s0[qi] = 0.0f; s1[qi] = 0.0f; }
        #pragma unroll
        for (int d4 = 0; d4 < 16; d4++) {
            float4 k0 = *(const float4*)&S_K[lane * 68 + d4 * 4];
            float4 k1 = *(const float4*)&S_K[(lane + 32) * 68 + d4 * 4];
            #pragma unroll
            for (int qi = 0; qi < 8; qi++) {
                float4 q4 = *(const float4*)&S_Q[(warp * 8 + qi) * 68 + d4 * 4];
                s0[qi] += q4.x * k0.x + q4.y * k0.y + q4.z * k0.z + q4.w * k0.w;
                s1[qi] += q4.x * k1.x + q4.y * k1.y + q4.z * k1.z + q4.w * k1.w;
            }
        }

        bool diag = (jt == qt);
        #pragma unroll
        for (int qi = 0; qi < 8; qi++) {
            float sc0 = s0[qi] * 0.125f;
            float sc1 = s1[qi] * 0.125f;
            int qrow = warp * 8 + qi;
            if (diag) {
                if (lane      > qrow) sc0 = -1e30f;
                if (lane + 32 > qrow) sc1 = -1e30f;
            }
            // tile max
            float mx = fmaxf(sc0, sc1);
            #pragma unroll
            for (int o = 16; o > 0; o >>= 1)
                mx = fmaxf(mx, __shfl_xor_sync(0xFFFFFFFFu, mx, o));
            float mnew = fmaxf(m[qi], mx);
            float corr = __expf(m[qi] - mnew);
            float p0 = __expf(sc0 - mnew);
            float p1 = __expf(sc1 - mnew);
            float ts = p0 + p1;
            #pragma unroll
            for (int o = 16; o > 0; o >>= 1)
                ts += __shfl_xor_sync(0xFFFFFFFFu, ts, o);
            l[qi] = l[qi] * corr + ts;
            m[qi] = mnew;
            a0[qi] *= corr;
            a1[qi] *= corr;
            S_P[(warp * 8 + qi) * 64 + lane]      = p0;
            S_P[(warp * 8 + qi) * 64 + lane + 32] = p1;
        }
        __syncwarp();

        // ---- AV: this lane owns d = lane and d = lane+32 ----
        #pragma unroll 4
        for (int j = 0; j < 64; j++) {
            float v0 = S_V[j * 68 + lane];
            float v1 = S_V[j * 68 + lane + 32];
            #pragma unroll
            for (int qi = 0; qi < 8; qi++) {
                float p = S_P[(warp * 8 + qi) * 64 + j];
                a0[qi] += p * v0;
                a1[qi] += p * v1;
            }
        }
    }

    // ---- output ----
    #pragma unroll
    for (int qi = 0; qi < 8; qi++) {
        int q = qt * 64 + warp * 8 + qi;
        float inv = 1.0f / l[qi];
        size_t o = ((size_t)(b * TT + q)) * CC + h * HD;
        y[o + lane]      = a0[qi] * inv;
        y[o + lane + 32] = a1[qi] * inv;
    }
}

// ---------------------------------------------------------------------------
// Host launcher
// ---------------------------------------------------------------------------
static void launch_gemm(const float* A, const float* W, const float* bias,
                        const float* res, float* C, int N, int K, int act)
{
    dim3 grid(N / 128, BT / 128);
    tc_gemm_kernel<<<grid, 256, GEMM_SMEM_BYTES>>>(A, W, bias, res, C, N, K, act);
}

extern "C" void kernel_launch(void* const* d_in, const int* in_sizes, int n_in,
                              void* d_out, int out_size)
{
    const int*   idx     = (const int*)  d_in[0];
    const float* wte     = (const float*)d_in[1];
    const float* wpe     = (const float*)d_in[2];
    const float* ln1w    = (const float*)d_in[3];
    const float* ln1b    = (const float*)d_in[4];
    const float* qkvw    = (const float*)d_in[5];
    const float* qkvb    = (const float*)d_in[6];
    const float* projw   = (const float*)d_in[7];
    const float* projb   = (const float*)d_in[8];
    const float* ln2w    = (const float*)d_in[9];
    const float* ln2b    = (const float*)d_in[10];
    const float* fcw     = (const float*)d_in[11];
    const float* fcb     = (const float*)d_in[12];
    const float* fcprojw = (const float*)d_in[13];
    const float* fcprojb = (const float*)d_in[14];
    const float* lnfw    = (const float*)d_in[15];
    const float* lnfb    = (const float*)d_in[16];
    float* out = (float*)d_out;

    cudaFuncSetAttribute(tc_gemm_kernel,
                         cudaFuncAttributeMaxDynamicSharedMemorySize,
                         GEMM_SMEM_BYTES);
    cudaFuncSetAttribute(attn_kernel2,
                         cudaFuncAttributeMaxDynamicSharedMemorySize,
                         ATTN_SMEM_BYTES);

    float *x, *h, *qkv, *y, *fch;
    cudaGetSymbolAddress((void**)&x,   g_x);
    cudaGetSymbolAddress((void**)&h,   g_h);
    cudaGetSymbolAddress((void**)&qkv, g_qkv);
    cudaGetSymbolAddress((void**)&y,   g_y);
    cudaGetSymbolAddress((void**)&fch, g_fch);

    embed_kernel<<<(BT * CC) / 256, 256>>>(idx, wte, wpe, x);

    for (int l = 0; l < NL; l++) {
        const float* l1w = ln1w + (size_t)l * CC;
        const float* l1b = ln1b + (size_t)l * CC;
        const float* qw  = qkvw + (size_t)l * C3 * CC;
        const float* qb  = qkvb + (size_t)l * C3;
        const float* pw  = projw + (size_t)l * CC * CC;
        const float* pb  = projb + (size_t)l * CC;
        const float* l2w = ln2w + (size_t)l * CC;
        const float* l2b = ln2b + (size_t)l * CC;
        const float* fw  = fcw  + (size_t)l * C4 * CC;
        const float* fb  = fcb  + (size_t)l * C4;
        const float* fpw = fcprojw + (size_t)l * CC * C4;
        const float* fpb = fcprojb + (size_t)l * CC;

        layernorm_kernel<<<BT, 256>>>(x, l1w, l1b, h);
        launch_gemm(h, qw, qb, nullptr, qkv, C3, CC, 0);
        attn_kernel2<<<dim3(TT / 64, NH, 2), 256, ATTN_SMEM_BYTES>>>(qkv, y);
        launch_gemm(y, pw, pb, x, x, CC, CC, 0);

        layernorm_kernel<<<BT, 256>>>(x, l2w, l2b, h);
        launch_gemm(h, fw, fb, nullptr, fch, C4, CC, 1);
        launch_gemm(fch, fpw, fpb, x, x, CC, C4, 0);
    }

    layernorm_kernel<<<BT, 256>>>(x, lnfw, lnfb, h);
    launch_gemm(h, wte, nullptr, nullptr, out, VP, CC, 0);
}